// round 5
// baseline (speedup 1.0000x reference)
#include <cuda_runtime.h>
#include <cstdint>
#include <cstddef>

// Problem constants
#define BATCH   1024
#define SEQ     512
#define NFEAT   64
#define HID     128
#define GATES   512          // 4*HID
#define NOUT    128

// LSTM persistent kernel config
#define NCTA    128
#define BR      8            // batch rows per CTA (1024/128)
#define LTHREADS 512
#define SMEM_K4 20           // k4 blocks of W_hh kept in smem (20*512*16B = 160 KB)
#define REG_K4  12           // k4 blocks register-cached per thread (12*4 float4 = 48 regs)

// Scratch (device globals; no allocations allowed)
__device__ float  g_xg[(size_t)BATCH * SEQ * GATES];   // precomputed x@W_ih^T + b_ih + b_hh, [bt][gate]
__device__ float4 g_Wq[32 * GATES];                    // repacked W_hh: [k4][row] float4 of W_hh[row][4k4..4k4+3]

// ---------------------------------------------------------------------------
// f32x2 packed FMA helper
// ---------------------------------------------------------------------------
__device__ __forceinline__ void ffma2(unsigned long long& d,
                                      unsigned long long a,
                                      unsigned long long b) {
    asm("fma.rn.f32x2 %0, %1, %2, %0;" : "+l"(d) : "l"(a), "l"(b));
}

__device__ __forceinline__ float hsum2(unsigned long long v) {
    float lo = __int_as_float((unsigned int)(v & 0xffffffffULL));
    float hi = __int_as_float((unsigned int)(v >> 32));
    return lo + hi;
}

__device__ __forceinline__ float sigmoid_f(float x) {
    return __fdividef(1.0f, 1.0f + __expf(-x));
}
__device__ __forceinline__ float tanh_f(float x) {
    // tanh(x) = 1 - 2/(e^{2x}+1); exact at +-inf via rcp.approx
    return 1.0f - __fdividef(2.0f, __expf(2.0f * x) + 1.0f);
}

// ---------------------------------------------------------------------------
// Kernel 0: repack W_hh [512][128] row-major -> g_Wq[k4][row]
// ---------------------------------------------------------------------------
__global__ void pack_whh_kernel(const float* __restrict__ Whh) {
    int n = threadIdx.x;   // 0..511
    const float4* row = (const float4*)(Whh + (size_t)n * HID);
#pragma unroll
    for (int k4 = 0; k4 < 32; k4++) {
        g_Wq[k4 * GATES + n] = row[k4];
    }
}

// ---------------------------------------------------------------------------
// Kernel 1: xg[bt][n] = sum_f x[bt][f] * W_ih[n][f] + b_ih[n] + b_hh[n]
// ---------------------------------------------------------------------------
__global__ __launch_bounds__(256) void xg_kernel(const float* __restrict__ x,
                                                 const float* __restrict__ Wih,
                                                 const float* __restrict__ b_ih,
                                                 const float* __restrict__ b_hh) {
    __shared__ float As[64][66];
    __shared__ float Bs[64][66];

    const int bt0 = blockIdx.x * 64;
    const int n0  = blockIdx.y * 64;
    const int tid = threadIdx.x;

    const float4* Ag = (const float4*)(x   + (size_t)bt0 * NFEAT);
    const float4* Bg = (const float4*)(Wih + (size_t)n0  * NFEAT);
#pragma unroll
    for (int p = 0; p < 4; p++) {
        int v = tid + p * 256;
        int m = v >> 4;
        int k = (v & 15) * 4;
        float4 qa = Ag[v];
        As[m][k] = qa.x; As[m][k+1] = qa.y; As[m][k+2] = qa.z; As[m][k+3] = qa.w;
        float4 qb = Bg[v];
        Bs[m][k] = qb.x; Bs[m][k+1] = qb.y; Bs[m][k+2] = qb.z; Bs[m][k+3] = qb.w;
    }
    __syncthreads();

    const int tx = tid & 31;
    const int ty = tid >> 5;

    unsigned long long acc[8][2];
#pragma unroll
    for (int i = 0; i < 8; i++)
#pragma unroll
        for (int j = 0; j < 2; j++) acc[i][j] = 0ULL;

#pragma unroll
    for (int k2 = 0; k2 < 32; k2++) {
        unsigned long long a2[8], b2[2];
#pragma unroll
        for (int i = 0; i < 8; i++)
            a2[i] = *(const unsigned long long*)&As[ty + i * 8][k2 * 2];
#pragma unroll
        for (int j = 0; j < 2; j++)
            b2[j] = *(const unsigned long long*)&Bs[tx + j * 32][k2 * 2];
#pragma unroll
        for (int i = 0; i < 8; i++)
#pragma unroll
            for (int j = 0; j < 2; j++)
                ffma2(acc[i][j], a2[i], b2[j]);
    }

    float bias[2];
#pragma unroll
    for (int j = 0; j < 2; j++) {
        int n = n0 + tx + j * 32;
        bias[j] = __ldg(&b_ih[n]) + __ldg(&b_hh[n]);
    }

#pragma unroll
    for (int i = 0; i < 8; i++) {
        int m = bt0 + ty + i * 8;
#pragma unroll
        for (int j = 0; j < 2; j++) {
            int n = n0 + tx + j * 32;
            g_xg[(size_t)m * GATES + n] = hsum2(acc[i][j]) + bias[j];
        }
    }
}

// ---------------------------------------------------------------------------
// Kernel 2: persistent LSTM, fused per-output scheme.
// Thread (rp, j), j = tid&127, rp = tid>>7, handles outputs (rp, j) and
// (rp+4, j): computes all 4 gate dots, applies nonlinearities, updates c
// (registers) and h (double-buffered smem). ONE barrier per step.
// Weights: k4 0..19 in smem; k4 20..31 register-cached (per-thread rows
// j, j+128, j+256, j+384 only). Zero L2 weight traffic in the loop.
// ---------------------------------------------------------------------------
extern __shared__ char smem_raw[];

__global__ __launch_bounds__(LTHREADS, 1) void lstm_kernel(
        const float* __restrict__ W_out,
        const float* __restrict__ b_out,
        float* __restrict__ out) {

    // smem carve: weights (SMEM_K4*512*16 = 163840B) | h double buffer (2*4096B)
    ulonglong2* w4s = (ulonglong2*)smem_raw;                       // [SMEM_K4][512]
    float* hbuf = (float*)(smem_raw + SMEM_K4 * GATES * 16);       // [2][8][128]

    const int tid = threadIdx.x;
    const int b0  = blockIdx.x * BR;
    const int j   = tid & 127;
    const int rp  = tid >> 7;          // 0..3; rows rp and rp+4

    const ulonglong2* Wg = (const ulonglong2*)g_Wq;

    // Load smem weight blocks (k4 0..SMEM_K4-1)
#pragma unroll
    for (int p = 0; p < SMEM_K4; p++) {
        int idx = tid + p * LTHREADS;
        w4s[idx] = Wg[idx];
    }
    // Register-cache upper weight blocks for this thread's 4 gate rows
    ulonglong2 wreg[REG_K4][4];
#pragma unroll
    for (int k = 0; k < REG_K4; k++)
#pragma unroll
        for (int g = 0; g < 4; g++)
            wreg[k][g] = Wg[(SMEM_K4 + k) * GATES + g * HID + j];

    // Zero h buffer 0
    hbuf[tid]            = 0.0f;
    hbuf[tid + LTHREADS] = 0.0f;
    __syncthreads();

    float cst[2] = {0.0f, 0.0f};

    for (int t = 0; t < SEQ; t++) {
        const int rb = t & 1;
        const float* __restrict__ hr = hbuf + rb * (BR * HID);
        float*       __restrict__ hw = hbuf + (rb ^ 1) * (BR * HID);

        // Prefetch xg for this step (independent of h; hides DRAM latency)
        float xg_v[2][4];
#pragma unroll
        for (int p = 0; p < 2; p++) {
            size_t base = ((size_t)((b0 + rp + p * 4) * SEQ + t)) * GATES + j;
#pragma unroll
            for (int g = 0; g < 4; g++)
                xg_v[p][g] = __ldg(&g_xg[base + g * HID]);
        }

        unsigned long long acc[2][4];
#pragma unroll
        for (int p = 0; p < 2; p++)
#pragma unroll
            for (int g = 0; g < 4; g++) acc[p][g] = 0ULL;

        // smem weight half: k4 0..SMEM_K4-1
#pragma unroll
        for (int k4 = 0; k4 < SMEM_K4; k4++) {
            ulonglong2 h0 = *(const ulonglong2*)&hr[rp * HID + k4 * 4];
            ulonglong2 h1 = *(const ulonglong2*)&hr[(rp + 4) * HID + k4 * 4];
#pragma unroll
            for (int g = 0; g < 4; g++) {
                ulonglong2 w = w4s[k4 * GATES + g * HID + j];
                ffma2(acc[0][g], h0.x, w.x);
                ffma2(acc[0][g], h0.y, w.y);
                ffma2(acc[1][g], h1.x, w.x);
                ffma2(acc[1][g], h1.y, w.y);
            }
        }
        // register weight half: k4 SMEM_K4..31
#pragma unroll
        for (int k = 0; k < REG_K4; k++) {
            int k4 = SMEM_K4 + k;
            ulonglong2 h0 = *(const ulonglong2*)&hr[rp * HID + k4 * 4];
            ulonglong2 h1 = *(const ulonglong2*)&hr[(rp + 4) * HID + k4 * 4];
#pragma unroll
            for (int g = 0; g < 4; g++) {
                ffma2(acc[0][g], h0.x, wreg[k][g].x);
                ffma2(acc[0][g], h0.y, wreg[k][g].y);
                ffma2(acc[1][g], h1.x, wreg[k][g].x);
                ffma2(acc[1][g], h1.y, wreg[k][g].y);
            }
        }

        // Nonlinearity + state update (fused, same thread)
#pragma unroll
        for (int p = 0; p < 2; p++) {
            int r = rp + p * 4;
            float gi = hsum2(acc[p][0]) + xg_v[p][0];
            float gf = hsum2(acc[p][1]) + xg_v[p][1];
            float gg = hsum2(acc[p][2]) + xg_v[p][2];
            float go = hsum2(acc[p][3]) + xg_v[p][3];
            float iv = sigmoid_f(gi);
            float fv = sigmoid_f(gf);
            float gv = tanh_f(gg);
            float ov = sigmoid_f(go);
            float cc = fv * cst[p] + iv * gv;
            cst[p] = cc;
            hw[r * HID + j] = ov * tanh_f(cc);
        }
        __syncthreads();   // h writes visible for next step (double buffer: no WAR)
    }

    // Final h is in buffer 0 (t=511 writes buffer (1^1)=0)
    const float* hf = hbuf;   // [8][128]

    // Output projection: out[b][o] = h[b] . W_out[o] + b_out[o]
#pragma unroll
    for (int p = 0; p < 2; p++) {
        int idx = tid + p * LTHREADS;      // 0..1023 -> (r, o)
        int r = idx >> 7;
        int o = idx & 127;
        const float4* wo = (const float4*)(W_out + (size_t)o * HID);
        const float4* hrr = (const float4*)&hf[r * HID];
        float s = __ldg(&b_out[o]);
#pragma unroll
        for (int k4 = 0; k4 < 32; k4++) {
            float4 w = wo[k4];
            float4 h = hrr[k4];
            s += w.x * h.x + w.y * h.y + w.z * h.z + w.w * h.w;
        }
        out[(size_t)(b0 + r) * NOUT + o] = s;
    }
}

// ---------------------------------------------------------------------------
// Launch
// ---------------------------------------------------------------------------
extern "C" void kernel_launch(void* const* d_in, const int* in_sizes, int n_in,
                              void* d_out, int out_size) {
    const float* x     = (const float*)d_in[0];
    const float* W_ih  = (const float*)d_in[1];
    const float* W_hh  = (const float*)d_in[2];
    const float* b_ih  = (const float*)d_in[3];
    const float* b_hh  = (const float*)d_in[4];
    const float* W_out = (const float*)d_in[5];
    const float* b_out = (const float*)d_in[6];
    float* out = (float*)d_out;

    const int lstm_smem = SMEM_K4 * GATES * 16 + 2 * BR * HID * 4;   // 163840 + 8192
    cudaFuncSetAttribute(lstm_kernel,
                         cudaFuncAttributeMaxDynamicSharedMemorySize, lstm_smem);

    pack_whh_kernel<<<1, GATES>>>(W_hh);

    dim3 grid1((BATCH * SEQ) / 64, GATES / 64);
    xg_kernel<<<grid1, 256>>>(x, W_ih, b_ih, b_hh);

    lstm_kernel<<<NCTA, LTHREADS, lstm_smem>>>(W_out, b_out, out);
}